// round 2
// baseline (speedup 1.0000x reference)
#include <cuda_runtime.h>
#include <math.h>
#include <stdint.h>

#define NQ    12
#define DIM   4096
#define TT    8
#define BB    32
#define SHOTS 256
#define KMAX  96
#define HALF  2048   // entries per CTA (2-CTA cluster per t)

// Final evolved states exp(-i t H)|init>, one complex vector per t.
__device__ float2 g_states[TT][DIM];

// ---------------------------------------------------------------------------
// helpers
// ---------------------------------------------------------------------------
__device__ __forceinline__ uint32_t smem_u32(const void* p) {
    uint32_t a;
    asm("{ .reg .u64 t; cvta.to.shared.u64 t, %1; cvt.u32.u64 %0, t; }"
        : "=r"(a) : "l"(p));
    return a;
}

__device__ __forceinline__ void mbar_wait_parity_cluster(uint32_t bar, uint32_t parity) {
    asm volatile(
        "{\n\t.reg .pred P;\n\t"
        "WAITL_%=:\n\t"
        "mbarrier.try_wait.parity.acquire.cluster.shared::cta.b64 P, [%0], %1, 0x989680;\n\t"
        "@P bra.uni WAITD_%=;\n\t"
        "bra.uni WAITL_%=;\n\t"
        "WAITD_%=:\n\t}"
        :: "r"(bar), "r"(parity) : "memory");
}

__device__ __forceinline__ void st_cluster_f32(uint32_t addr, float v) {
    asm volatile("st.shared::cluster.b32 [%0], %1;"
                 :: "r"(addr), "r"(__float_as_uint(v)) : "memory");
}

// ---------------------------------------------------------------------------
// Kernel B: Chebyshev evolution, one 2-CTA cluster per t.
// CTA rank owns global indices with bit 11 == rank. Local layout:
//   local = (tid<<3) | e,  e = bits 0..2 (registers), tid = bits 3..10.
// Taps: bits 0-2 regs, bits 3-10 local smem (LDS.128), bit 11 peer mirror.
// Mirror ping-pong + mbarrier handshake refreshes peer half each term.
// ---------------------------------------------------------------------------
__global__ void __cluster_dims__(2, 1, 1) __launch_bounds__(256, 1)
evolve_kernel(const int* __restrict__ d_init,
              const float* __restrict__ d_ts,
              const float* __restrict__ d_px,
              const float* __restrict__ d_pzz)
{
    __shared__ __align__(16) float cur_s[HALF];
    __shared__ __align__(16) float mir[2][HALF];
    __shared__ float s_cr[KMAX + 1];
    __shared__ float s_ci[KMAX + 1];
    __shared__ int   s_K;
    __shared__ __align__(8) unsigned long long s_bar[2];

    const int tid = threadIdx.x;
    uint32_t rank;
    asm("mov.u32 %0, %%cluster_ctarank;" : "=r"(rank));
    const uint32_t peer = rank ^ 1u;
    const int t = blockIdx.x >> 1;

    // --- parameters, lambda bound ---
    float px[NQ];
    float lambda = 0.f;
#pragma unroll
    for (int i = 0; i < NQ; i++) { px[i] = d_px[i]; lambda += fabsf(px[i]); }
    float pzz[NQ - 1];
#pragma unroll
    for (int i = 0; i < NQ - 1; i++) { pzz[i] = d_pzz[i]; lambda += fabsf(pzz[i]); }
    if (lambda < 1e-20f) lambda = 1e-20f;
    const float inv_l = 1.0f / lambda;
#pragma unroll
    for (int i = 0; i < NQ; i++) px[i] *= inv_l;

    // per-owned-entry scaled diagonal (ZZ part); global s = (rank<<11)|local
    float diag[8];
#pragma unroll
    for (int e = 0; e < 8; e++) {
        const int s = (int)(rank << 11) | (tid << 3) | e;
        float d = 0.f;
#pragma unroll
        for (int i = 0; i < NQ - 1; i++) {
            const int bi = (s >> i) & 1;
            const int bj = (s >> (i + 1)) & 1;
            d += (bi == bj) ? pzz[i] : -pzz[i];
        }
        diag[e] = d * inv_l;
    }

    // --- thread 0: Bessel coefficients (Miller downward recurrence) ---
    if (tid == 0) {
        double x = (double)d_ts[t] * (double)lambda;
        if (x < 1e-5) x = 1e-5;
        int K = (int)ceil(x) + 25;
        if (K > KMAX) K = KMAX;
        const int M = K + 14;
        double v[KMAX + 16];
        v[M] = 1e-30;
        const double inv_x = 1.0 / x;
        double up = 0.0;
        for (int k = M; k >= 1; k--) {
            const double nv = (2.0 * (double)k * inv_x) * v[k] - up;
            up = v[k];
            v[k - 1] = nv;
        }
        double S = v[0];
        for (int m = 2; m <= M; m += 2) S += 2.0 * v[m];
        const double invS = 1.0 / S;
        for (int k = 0; k <= K; k++) {
            const double Jk = v[k] * invS;
            const double c  = (k == 0) ? Jk : 2.0 * Jk;
            float cr = 0.f, ci = 0.f;
            switch (k & 3) {
                case 0: cr = (float)c;  break;
                case 1: ci = (float)-c; break;
                case 2: cr = (float)-c; break;
                case 3: ci = (float)c;  break;
            }
            s_cr[k] = cr;
            s_ci[k] = ci;
        }
        s_K = K;
        // init mbarriers (arrive count 1: single elected arrival per phase)
        asm volatile("mbarrier.init.shared.b64 [%0], 1;" :: "r"(smem_u32(&s_bar[0])) : "memory");
        asm volatile("mbarrier.init.shared.b64 [%0], 1;" :: "r"(smem_u32(&s_bar[1])) : "memory");
    }
    __syncthreads();

    // --- state init: phi_0 = e_init ---
    const int init = *d_init;
    float cur[8], prev[8], psr[8], psi[8];
    const int mybase = tid << 3;
#pragma unroll
    for (int e = 0; e < 8; e++) {
        const int local = mybase | e;
        const int gs = (int)(rank << 11) | local;
        const int gp = (int)(peer << 11) | local;
        const float v  = (gs == init) ? 1.f : 0.f;
        cur[e]  = v;
        prev[e] = 0.f;
        cur_s[local]  = v;
        mir[1][local] = (gp == init) ? 1.f : 0.f;  // peer's phi_0, known globally
        mir[0][local] = 0.f;
        psr[e] = s_cr[0] * v;
        psi[e] = 0.f;
    }
    __syncthreads();
    // cluster-wide: barriers + mirrors initialized everywhere before any arrives
    asm volatile("barrier.cluster.arrive.aligned;" ::: "memory");
    asm volatile("barrier.cluster.wait.aligned;"   ::: "memory");

    const int K = s_K;
    const uint32_t bar0 = smem_u32(&s_bar[0]);
    const uint32_t bar1 = smem_u32(&s_bar[1]);
    // loop-invariant mapped remote addresses (peer's mirror rows for my chunk)
    uint32_t rmir0, rmir1, rbar0, rbar1;
    {
        uint32_t l0 = smem_u32(&mir[0][mybase]);
        uint32_t l1 = smem_u32(&mir[1][mybase]);
        asm("mapa.shared::cluster.u32 %0, %1, %2;" : "=r"(rmir0) : "r"(l0), "r"(peer));
        asm("mapa.shared::cluster.u32 %0, %1, %2;" : "=r"(rmir1) : "r"(l1), "r"(peer));
        asm("mapa.shared::cluster.u32 %0, %1, %2;" : "=r"(rbar0) : "r"(bar0), "r"(peer));
        asm("mapa.shared::cluster.u32 %0, %1, %2;" : "=r"(rbar1) : "r"(bar1), "r"(peer));
    }

    int ph0 = 0, ph1 = 0;
    const float4* curv = reinterpret_cast<const float4*>(cur_s);
    const int f4b = mybase >> 2;

    for (int j = 1; j <= K; j++) {
        const int p = j & 1;
        if (j >= 2) {
            if (p) { mbar_wait_parity_cluster(bar1, (uint32_t)ph1); ph1 ^= 1; }
            else   { mbar_wait_parity_cluster(bar0, (uint32_t)ph0); ph0 ^= 1; }
        }

        float acc[8];
#pragma unroll
        for (int e = 0; e < 8; e++) {
            float a = diag[e] * cur[e];
            a = fmaf(px[0], cur[e ^ 1], a);
            a = fmaf(px[1], cur[e ^ 2], a);
            a = fmaf(px[2], cur[e ^ 4], a);
            acc[e] = a;
        }
        // local smem taps, bits 3..10 (vectorized)
#pragma unroll
        for (int b = 3; b <= 10; b++) {
            const int tb = (mybase ^ (1 << b)) >> 2;
            const float4 lo = curv[tb];
            const float4 hi = curv[tb + 1];
            const float c = px[b];
            acc[0] = fmaf(c, lo.x, acc[0]); acc[1] = fmaf(c, lo.y, acc[1]);
            acc[2] = fmaf(c, lo.z, acc[2]); acc[3] = fmaf(c, lo.w, acc[3]);
            acc[4] = fmaf(c, hi.x, acc[4]); acc[5] = fmaf(c, hi.y, acc[5]);
            acc[6] = fmaf(c, hi.z, acc[6]); acc[7] = fmaf(c, hi.w, acc[7]);
        }
        // peer tap, bit 11
        {
            const float4* mv = reinterpret_cast<const float4*>(mir[p]);
            const float4 lo = mv[f4b];
            const float4 hi = mv[f4b + 1];
            const float c = px[11];
            acc[0] = fmaf(c, lo.x, acc[0]); acc[1] = fmaf(c, lo.y, acc[1]);
            acc[2] = fmaf(c, lo.z, acc[2]); acc[3] = fmaf(c, lo.w, acc[3]);
            acc[4] = fmaf(c, hi.x, acc[4]); acc[5] = fmaf(c, hi.y, acc[5]);
            acc[6] = fmaf(c, hi.z, acc[6]); acc[7] = fmaf(c, hi.w, acc[7]);
        }
        float nxt[8];
        if (j > 1) {
#pragma unroll
            for (int e = 0; e < 8; e++) nxt[e] = fmaf(2.f, acc[e], -prev[e]);
        } else {
#pragma unroll
            for (int e = 0; e < 8; e++) nxt[e] = acc[e];
        }

        __syncthreads();   // everyone done reading cur_s / mir[p]

        // local store (vectorized)
        {
            float4* cs = reinterpret_cast<float4*>(cur_s);
            cs[f4b]     = make_float4(nxt[0], nxt[1], nxt[2], nxt[3]);
            cs[f4b + 1] = make_float4(nxt[4], nxt[5], nxt[6], nxt[7]);
        }
        // remote store into peer's mir[p^1]
        if (j < K) {
            const uint32_t ra = p ? rmir0 : rmir1;   // mir[p^1] mapped
#pragma unroll
            for (int e = 0; e < 8; e++) st_cluster_f32(ra + 4u * e, nxt[e]);
        }
        const float cr = s_cr[j], ci = s_ci[j];
#pragma unroll
        for (int e = 0; e < 8; e++) {
            prev[e] = cur[e];
            cur[e]  = nxt[e];
            psr[e]  = fmaf(cr, nxt[e], psr[e]);
            psi[e]  = fmaf(ci, nxt[e], psi[e]);
        }

        __syncthreads();   // all local+remote stores issued by all threads

        if (j < K && tid == 0) {
            asm volatile("fence.acq_rel.cluster;" ::: "memory");
            const uint32_t rb = p ? rbar0 : rbar1;   // peer's B[p^1]
            asm volatile("mbarrier.arrive.release.cluster.shared::cluster.b64 _, [%0];"
                         :: "r"(rb) : "memory");
        }
    }

#pragma unroll
    for (int e = 0; e < 8; e++)
        g_states[t][(rank << 11) | (mybase | e)] = make_float2(psr[e], psi[e]);

    asm volatile("barrier.cluster.arrive.aligned;" ::: "memory");
    asm volatile("barrier.cluster.wait.aligned;"   ::: "memory");
}

// ---------------------------------------------------------------------------
// Kernel C: per-(t,b) basis rotation, radix-4 fused over non-Z qubits,
// then gather of 256 shot probabilities.
// Pauli position i acts on bit (N-1-i) of the state index.
// ---------------------------------------------------------------------------
__global__ __launch_bounds__(256)
void measure_kernel(const int* __restrict__ d_pauli,
                    const int* __restrict__ d_idx,
                    float* __restrict__ d_out)
{
    __shared__ float re[DIM];
    __shared__ float im[DIM];
    __shared__ int nzm[NQ];
    __shared__ int nzp[NQ];
    __shared__ int s_nnz;

    const int tid = threadIdx.x;
    const int b   = blockIdx.x;
    const int t   = blockIdx.y;

#pragma unroll
    for (int r = 0; r < DIM / 256; r++) {
        const int s = tid + (r << 8);
        const float2 v = g_states[t][s];
        re[s] = v.x;
        im[s] = v.y;
    }
    if (tid == 0) {
        int c = 0;
        for (int m = NQ - 1; m >= 0; m--) {
            const int p = d_pauli[b * NQ + (NQ - 1 - m)];
            if (p != 2) { nzm[c] = m; nzp[c] = p; c++; }
        }
        s_nnz = c;
    }
    __syncthreads();

    const int nnz = s_nnz;
    int i = 0;
    // radix-4: two non-Z qubits per sweep (mh > ml since list is descending)
    for (; i + 1 < nnz; i += 2) {
        const int mh = nzm[i], ml = nzm[i + 1];
        const int ph_ = nzp[i], pl = nzp[i + 1];
        const int lml = (1 << ml) - 1;
        const int lmh = (1 << mh) - 1;
#pragma unroll
        for (int r = 0; r < 4; r++) {
            const int g  = tid + (r << 8);
            const int x  = ((g & ~lml) << 1) | (g & lml);
            const int s00 = ((x & ~lmh) << 1) | (x & lmh);
            const int s01 = s00 | (1 << ml);
            const int s10 = s00 | (1 << mh);
            const int s11 = s10 | (1 << ml);
            const float r00 = re[s00], i00 = im[s00];
            const float r01 = re[s01], i01 = im[s01];
            const float r10 = re[s10], i10 = im[s10];
            const float r11 = re[s11], i11 = im[s11];
            // gate pl on (00,01) and (10,11)
            float a0r, a0i, a1r, a1i, b0r, b0i, b1r, b1i;
            if (pl == 0) {
                a0r = r00 + r01; a0i = i00 + i01; a1r = r00 - r01; a1i = i00 - i01;
                b0r = r10 + r11; b0i = i10 + i11; b1r = r10 - r11; b1i = i10 - i11;
            } else {
                a0r = r00 + i01; a0i = i00 - r01; a1r = r00 - i01; a1i = i00 + r01;
                b0r = r10 + i11; b0i = i10 - r11; b1r = r10 - i11; b1i = i10 + r11;
            }
            // gate ph_ on (00,10) and (01,11)
            float o00r, o00i, o01r, o01i, o10r, o10i, o11r, o11i;
            if (ph_ == 0) {
                o00r = a0r + b0r; o00i = a0i + b0i; o10r = a0r - b0r; o10i = a0i - b0i;
                o01r = a1r + b1r; o01i = a1i + b1i; o11r = a1r - b1r; o11i = a1i - b1i;
            } else {
                o00r = a0r + b0i; o00i = a0i - b0r; o10r = a0r - b0i; o10i = a0i + b0r;
                o01r = a1r + b1i; o01i = a1i - b1r; o11r = a1r - b1i; o11i = a1i + b1r;
            }
            re[s00] = o00r * 0.5f; im[s00] = o00i * 0.5f;
            re[s01] = o01r * 0.5f; im[s01] = o01i * 0.5f;
            re[s10] = o10r * 0.5f; im[s10] = o10i * 0.5f;
            re[s11] = o11r * 0.5f; im[s11] = o11i * 0.5f;
        }
        __syncthreads();
    }
    // leftover single non-Z qubit
    if (i < nnz) {
        const int m = nzm[i], p = nzp[i];
        const int lm = (1 << m) - 1;
        const float s2 = 0.70710678118654752f;
#pragma unroll
        for (int r = 0; r < 8; r++) {
            const int q  = tid + (r << 8);
            const int s0 = ((q & ~lm) << 1) | (q & lm);
            const int s1 = s0 | (1 << m);
            const float r0 = re[s0], i0 = im[s0];
            const float r1 = re[s1], i1 = im[s1];
            float nr0, ni0, nr1, ni1;
            if (p == 0) { nr0 = r0 + r1; ni0 = i0 + i1; nr1 = r0 - r1; ni1 = i0 - i1; }
            else        { nr0 = r0 + i1; ni0 = i0 - r1; nr1 = r0 - i1; ni1 = i0 + r1; }
            re[s0] = nr0 * s2; im[s0] = ni0 * s2;
            re[s1] = nr1 * s2; im[s1] = ni1 * s2;
        }
        __syncthreads();
    }

    const int base = (t * BB + b) * SHOTS;
    const int idx  = d_idx[base + tid];
    const float pr = re[idx];
    const float pi = im[idx];
    d_out[base + tid] = pr * pr + pi * pi;
}

// ---------------------------------------------------------------------------
extern "C" void kernel_launch(void* const* d_in, const int* in_sizes, int n_in,
                              void* d_out, int out_size)
{
    const int*   d_init  = (const int*)  d_in[0];
    const float* d_ts    = (const float*)d_in[1];
    const int*   d_pauli = (const int*)  d_in[2];
    const int*   d_idx   = (const int*)  d_in[3];
    const float* d_px    = (const float*)d_in[4];
    const float* d_pzz   = (const float*)d_in[5];

    evolve_kernel<<<TT * 2, 256>>>(d_init, d_ts, d_px, d_pzz);
    measure_kernel<<<dim3(BB, TT), 256>>>(d_pauli, d_idx, (float*)d_out);
}

// round 3
// speedup vs baseline: 1.9870x; 1.9870x over previous
#include <cuda_runtime.h>
#include <math.h>
#include <stdint.h>

#define NQ    12
#define DIM   4096
#define TT    8
#define BB    32
#define SHOTS 256
#define KMAX  80

// Final evolved states exp(-i t H)|init>, one complex vector per t.
__device__ float2 g_states[TT][DIM];

// ---------------------------------------------------------------------------
// Kernel B: Chebyshev evolution. One 512-thread CTA per t, state in smem.
//   H' = H/lambda, x = t*lambda,  exp(-ixH') = sum_k (2-d_k0)(-i)^k J_k(x) T_k(H')
//   phi_{k+1} = 2 H' phi_k - phi_{k-1}   (all phi real)
// Thread layout: entry s = (tid<<3)|e. Bits 0-2 taps from registers,
// bits 3-11 taps via loop-invariant LDS.128 from double-buffered smem.
// ---------------------------------------------------------------------------
__global__ __launch_bounds__(512, 1)
void evolve_kernel(const int* __restrict__ d_init,
                   const float* __restrict__ d_ts,
                   const float* __restrict__ d_px,
                   const float* __restrict__ d_pzz)
{
    __shared__ __align__(16) float buf0[DIM];
    __shared__ __align__(16) float buf1[DIM];
    __shared__ float s_cr[KMAX + 1];
    __shared__ float s_ci[KMAX + 1];
    __shared__ int   s_K;

    const int tid = threadIdx.x;
    const int t   = blockIdx.x;

    // --- parameters + spectral bound ---
    float px[NQ];
    float lambda = 0.f;
#pragma unroll
    for (int i = 0; i < NQ; i++) { px[i] = d_px[i]; lambda += fabsf(px[i]); }
    float pzz[NQ - 1];
#pragma unroll
    for (int i = 0; i < NQ - 1; i++) { pzz[i] = d_pzz[i]; lambda += fabsf(pzz[i]); }
    if (lambda < 1e-20f) lambda = 1e-20f;
    const float inv_l = 1.0f / lambda;
#pragma unroll
    for (int i = 0; i < NQ; i++) px[i] *= inv_l;

    const int mybase = tid << 3;

    // scaled diagonal for owned entries
    float diag[8];
#pragma unroll
    for (int e = 0; e < 8; e++) {
        const int s = mybase | e;
        float d = 0.f;
#pragma unroll
        for (int i = 0; i < NQ - 1; i++) {
            const int bi = (s >> i) & 1;
            const int bj = (s >> (i + 1)) & 1;
            d += (bi == bj) ? pzz[i] : -pzz[i];
        }
        diag[e] = d * inv_l;
    }

    // --- thread 0: Bessel coefficients J_k(x), Miller downward recurrence ---
    if (tid == 0) {
        double x = (double)d_ts[t] * (double)lambda;
        if (x < 1e-5) x = 1e-5;
        int K = (int)ceil(x) + 16;
        if (K > KMAX) K = KMAX;
        if (K < 2)    K = 2;
        const int M = K + 14;
        double v[KMAX + 16];
        v[M] = 1e-30;
        const double inv_x = 1.0 / x;
        double up = 0.0;
        for (int k = M; k >= 1; k--) {
            const double nv = (2.0 * (double)k * inv_x) * v[k] - up;
            up = v[k];
            v[k - 1] = nv;
        }
        double S = v[0];
        for (int m = 2; m <= M; m += 2) S += 2.0 * v[m];
        const double invS = 1.0 / S;
        for (int k = 0; k <= K; k++) {
            const double Jk = v[k] * invS;
            const double c  = (k == 0) ? Jk : 2.0 * Jk;
            float cr = 0.f, ci = 0.f;
            switch (k & 3) {             // (-i)^k
                case 0: cr = (float)c;  break;
                case 1: ci = (float)-c; break;
                case 2: cr = (float)-c; break;
                case 3: ci = (float)c;  break;
            }
            s_cr[k] = cr;
            s_ci[k] = ci;
        }
        s_K = K;
    }
    __syncthreads();

    const int K    = s_K;
    const int init = *d_init;

    // --- phi_0 = e_init ; phi_1 = H' e_init (analytic: one nonzero column) ---
    float cur[8], prev[8], psr[8], psi[8];
#pragma unroll
    for (int e = 0; e < 8; e++) {
        const int s  = mybase | e;
        const float p0 = (s == init) ? 1.f : 0.f;
        // H'[s, init]: diagonal if s==init, px[i] if s = init ^ (1<<i)
        float p1 = (s == init) ? diag[e] : 0.f;
        const int d = s ^ init;
#pragma unroll
        for (int i = 0; i < NQ; i++)
            if (d == (1 << i)) p1 = px[i];
        prev[e] = p0;
        cur[e]  = p1;
        buf0[s] = p1;                    // buf0 holds phi_1
        psr[e]  = s_cr[0] * p0;          // k=0 term (real)
        psi[e]  = s_ci[1] * p1;          // k=1 term (imag)
    }
    __syncthreads();

    // loop-invariant partner quad indices for tap bits 3..11
    int pq[9];
#pragma unroll
    for (int b = 3; b <= 11; b++)
        pq[b - 3] = (mybase ^ (1 << b)) >> 2;
    const int f4own = mybase >> 2;

#define CHEB_STEP(SRC, DST, KK)                                              \
    do {                                                                     \
        const float4* sv = reinterpret_cast<const float4*>(SRC);            \
        float4*       dv = reinterpret_cast<float4*>(DST);                  \
        float acc[8];                                                        \
        _Pragma("unroll")                                                    \
        for (int e = 0; e < 8; e++) {                                        \
            float a = diag[e] * cur[e];                                      \
            a = fmaf(px[0], cur[e ^ 1], a);                                  \
            a = fmaf(px[1], cur[e ^ 2], a);                                  \
            a = fmaf(px[2], cur[e ^ 4], a);                                  \
            acc[e] = a;                                                      \
        }                                                                    \
        _Pragma("unroll")                                                    \
        for (int bi = 0; bi < 9; bi++) {                                     \
            const float4 lo = sv[pq[bi]];                                    \
            const float4 hi = sv[pq[bi] + 1];                                \
            const float  c  = px[bi + 3];                                    \
            acc[0] = fmaf(c, lo.x, acc[0]); acc[1] = fmaf(c, lo.y, acc[1]);  \
            acc[2] = fmaf(c, lo.z, acc[2]); acc[3] = fmaf(c, lo.w, acc[3]);  \
            acc[4] = fmaf(c, hi.x, acc[4]); acc[5] = fmaf(c, hi.y, acc[5]);  \
            acc[6] = fmaf(c, hi.z, acc[6]); acc[7] = fmaf(c, hi.w, acc[7]);  \
        }                                                                    \
        const float cr = s_cr[KK], ci = s_ci[KK];                            \
        float nxt[8];                                                        \
        _Pragma("unroll")                                                    \
        for (int e = 0; e < 8; e++) {                                        \
            nxt[e] = fmaf(2.f, acc[e], -prev[e]);                            \
            prev[e] = cur[e];                                                \
            cur[e]  = nxt[e];                                                \
            psr[e]  = fmaf(cr, nxt[e], psr[e]);                              \
            psi[e]  = fmaf(ci, nxt[e], psi[e]);                              \
        }                                                                    \
        dv[f4own]     = make_float4(nxt[0], nxt[1], nxt[2], nxt[3]);         \
        dv[f4own + 1] = make_float4(nxt[4], nxt[5], nxt[6], nxt[7]);         \
        __syncthreads();                                                     \
    } while (0)

    for (int k = 2; k <= K; k += 2) {
        CHEB_STEP(buf0, buf1, k);        // even k: phi in buf0 -> buf1
        if (k + 1 <= K)
            CHEB_STEP(buf1, buf0, k + 1);
    }
#undef CHEB_STEP

#pragma unroll
    for (int e = 0; e < 8; e++)
        g_states[t][mybase | e] = make_float2(psr[e], psi[e]);
}

// ---------------------------------------------------------------------------
// Kernel C: per-(t,b) basis rotation, radix-4 fused over non-Z qubits,
// then gather of 256 shot probabilities. 512 threads.
// Pauli position i acts on bit (N-1-i) of the state index.
// ---------------------------------------------------------------------------
__global__ __launch_bounds__(512)
void measure_kernel(const int* __restrict__ d_pauli,
                    const int* __restrict__ d_idx,
                    float* __restrict__ d_out)
{
    __shared__ float re[DIM];
    __shared__ float im[DIM];
    __shared__ int p_raw[NQ];
    __shared__ int nzm[NQ];
    __shared__ int nzp[NQ];
    __shared__ int s_nnz;

    const int tid = threadIdx.x;
    const int b   = blockIdx.x;
    const int t   = blockIdx.y;

    if (tid < NQ) p_raw[tid] = d_pauli[b * NQ + tid];

#pragma unroll
    for (int r = 0; r < DIM / 512; r++) {
        const int s = tid + (r << 9);
        const float2 v = g_states[t][s];
        re[s] = v.x;
        im[s] = v.y;
    }
    __syncthreads();

    if (tid == 0) {
        int c = 0;
        for (int m = NQ - 1; m >= 0; m--) {
            const int p = p_raw[NQ - 1 - m];
            if (p != 2) { nzm[c] = m; nzp[c] = p; c++; }
        }
        s_nnz = c;
    }
    __syncthreads();

    const int nnz = s_nnz;
    int i = 0;
    // radix-4: two non-Z qubits per sweep (mh > ml; list descending)
    for (; i + 1 < nnz; i += 2) {
        const int mh = nzm[i], ml = nzm[i + 1];
        const int ph_ = nzp[i], pl = nzp[i + 1];
        const int lml = (1 << ml) - 1;
        const int lmh = (1 << mh) - 1;
#pragma unroll
        for (int r = 0; r < (DIM / 4) / 512; r++) {
            const int g  = tid + (r << 9);
            const int x  = ((g & ~lml) << 1) | (g & lml);
            const int s00 = ((x & ~lmh) << 1) | (x & lmh);
            const int s01 = s00 | (1 << ml);
            const int s10 = s00 | (1 << mh);
            const int s11 = s10 | (1 << ml);
            const float r00 = re[s00], i00 = im[s00];
            const float r01 = re[s01], i01 = im[s01];
            const float r10 = re[s10], i10 = im[s10];
            const float r11 = re[s11], i11 = im[s11];
            float a0r, a0i, a1r, a1i, b0r, b0i, b1r, b1i;
            if (pl == 0) {
                a0r = r00 + r01; a0i = i00 + i01; a1r = r00 - r01; a1i = i00 - i01;
                b0r = r10 + r11; b0i = i10 + i11; b1r = r10 - r11; b1i = i10 - i11;
            } else {
                a0r = r00 + i01; a0i = i00 - r01; a1r = r00 - i01; a1i = i00 + r01;
                b0r = r10 + i11; b0i = i10 - r11; b1r = r10 - i11; b1i = i10 + r11;
            }
            float o00r, o00i, o01r, o01i, o10r, o10i, o11r, o11i;
            if (ph_ == 0) {
                o00r = a0r + b0r; o00i = a0i + b0i; o10r = a0r - b0r; o10i = a0i - b0i;
                o01r = a1r + b1r; o01i = a1i + b1i; o11r = a1r - b1r; o11i = a1i - b1i;
            } else {
                o00r = a0r + b0i; o00i = a0i - b0r; o10r = a0r - b0i; o10i = a0i + b0r;
                o01r = a1r + b1i; o01i = a1i - b1r; o11r = a1r - b1i; o11i = a1i + b1r;
            }
            re[s00] = o00r * 0.5f; im[s00] = o00i * 0.5f;
            re[s01] = o01r * 0.5f; im[s01] = o01i * 0.5f;
            re[s10] = o10r * 0.5f; im[s10] = o10i * 0.5f;
            re[s11] = o11r * 0.5f; im[s11] = o11i * 0.5f;
        }
        __syncthreads();
    }
    // leftover single non-Z qubit
    if (i < nnz) {
        const int m = nzm[i], p = nzp[i];
        const int lm = (1 << m) - 1;
        const float s2 = 0.70710678118654752f;
#pragma unroll
        for (int r = 0; r < (DIM / 2) / 512; r++) {
            const int q  = tid + (r << 9);
            const int s0 = ((q & ~lm) << 1) | (q & lm);
            const int s1 = s0 | (1 << m);
            const float r0 = re[s0], i0 = im[s0];
            const float r1 = re[s1], i1 = im[s1];
            float nr0, ni0, nr1, ni1;
            if (p == 0) { nr0 = r0 + r1; ni0 = i0 + i1; nr1 = r0 - r1; ni1 = i0 - i1; }
            else        { nr0 = r0 + i1; ni0 = i0 - r1; nr1 = r0 - i1; ni1 = i0 + r1; }
            re[s0] = nr0 * s2; im[s0] = ni0 * s2;
            re[s1] = nr1 * s2; im[s1] = ni1 * s2;
        }
        __syncthreads();
    }

    if (tid < SHOTS) {
        const int base = (t * BB + b) * SHOTS;
        const int idx  = d_idx[base + tid];
        const float pr = re[idx];
        const float pi = im[idx];
        d_out[base + tid] = pr * pr + pi * pi;
    }
}

// ---------------------------------------------------------------------------
extern "C" void kernel_launch(void* const* d_in, const int* in_sizes, int n_in,
                              void* d_out, int out_size)
{
    const int*   d_init  = (const int*)  d_in[0];
    const float* d_ts    = (const float*)d_in[1];
    const int*   d_pauli = (const int*)  d_in[2];
    const int*   d_idx   = (const int*)  d_in[3];
    const float* d_px    = (const float*)d_in[4];
    const float* d_pzz   = (const float*)d_in[5];

    evolve_kernel<<<TT, 512>>>(d_init, d_ts, d_px, d_pzz);
    measure_kernel<<<dim3(BB, TT), 512>>>(d_pauli, d_idx, (float*)d_out);
}

// round 4
// speedup vs baseline: 2.7286x; 1.3732x over previous
#include <cuda_runtime.h>
#include <math.h>
#include <stdint.h>

#define NQ    12
#define DIM   4096
#define TT    8
#define BB    32
#define SHOTS 256
#define KMAX  80

// Final evolved states exp(-i t H)|init>, one complex vector per t.
__device__ float2 g_states[TT][DIM];

// ---------------------------------------------------------------------------
// Kernel B: Chebyshev evolution. One 512-thread CTA per t, state in smem.
//   H' = H/lambda, x = t*lambda,  exp(-ixH') = sum_k (2-d_k0)(-i)^k J_k(x) T_k(H')
//   phi_{k+1} = 2 H' phi_k - phi_{k-1}   (all phi real)
// Ownership: s = (e<<10)|(tid<<1)|c, e=0..3, c=0..1 (8 entries/thread).
// Register taps: bits 0,10,11. Smem taps: bits 1..9 via conflict-free LDS.64.
// State buffers stored as float2 pairs: pair index (e<<9)|tid.
// ---------------------------------------------------------------------------
__global__ __launch_bounds__(512, 1)
void evolve_kernel(const int* __restrict__ d_init,
                   const float* __restrict__ d_ts,
                   const float* __restrict__ d_px,
                   const float* __restrict__ d_pzz)
{
    __shared__ __align__(16) float2 buf0[DIM / 2];
    __shared__ __align__(16) float2 buf1[DIM / 2];
    __shared__ float s_cr[KMAX + 1];
    __shared__ float s_ci[KMAX + 1];
    __shared__ int   s_K;

    const int tid = threadIdx.x;
    const int t   = blockIdx.x;

    // --- parameters + spectral bound ---
    float px[NQ];
    float lambda = 0.f;
#pragma unroll
    for (int i = 0; i < NQ; i++) { px[i] = d_px[i]; lambda += fabsf(px[i]); }
    float pzz[NQ - 1];
#pragma unroll
    for (int i = 0; i < NQ - 1; i++) { pzz[i] = d_pzz[i]; lambda += fabsf(pzz[i]); }
    if (lambda < 1e-20f) lambda = 1e-20f;
    const float inv_l = 1.0f / lambda;
#pragma unroll
    for (int i = 0; i < NQ; i++) px[i] *= inv_l;

    // owned entry indices: s(e,c) = (e<<10) | (tid<<1) | c ; flat idx = e*2+c
    // scaled diagonal for owned entries
    float diag[8];
#pragma unroll
    for (int e = 0; e < 4; e++) {
#pragma unroll
        for (int c = 0; c < 2; c++) {
            const int s = (e << 10) | (tid << 1) | c;
            float d = 0.f;
#pragma unroll
            for (int i = 0; i < NQ - 1; i++) {
                const int bi = (s >> i) & 1;
                const int bj = (s >> (i + 1)) & 1;
                d += (bi == bj) ? pzz[i] : -pzz[i];
            }
            diag[e * 2 + c] = d * inv_l;
        }
    }

    // --- thread 0: Bessel coefficients J_k(x), Miller downward recurrence ---
    if (tid == 0) {
        double x = (double)d_ts[t] * (double)lambda;
        if (x < 1e-5) x = 1e-5;
        int K = (int)ceil(x) + 16;
        if (K > KMAX) K = KMAX;
        if (K < 2)    K = 2;
        const int M = K + 14;
        double v[KMAX + 16];
        v[M] = 1e-30;
        const double inv_x = 1.0 / x;
        double up = 0.0;
        for (int k = M; k >= 1; k--) {
            const double nv = (2.0 * (double)k * inv_x) * v[k] - up;
            up = v[k];
            v[k - 1] = nv;
        }
        double S = v[0];
        for (int m = 2; m <= M; m += 2) S += 2.0 * v[m];
        const double invS = 1.0 / S;
        for (int k = 0; k <= K; k++) {
            const double Jk = v[k] * invS;
            const double c  = (k == 0) ? Jk : 2.0 * Jk;
            float cr = 0.f, ci = 0.f;
            switch (k & 3) {             // (-i)^k
                case 0: cr = (float)c;  break;
                case 1: ci = (float)-c; break;
                case 2: cr = (float)-c; break;
                case 3: ci = (float)c;  break;
            }
            s_cr[k] = cr;
            s_ci[k] = ci;
        }
        s_K = K;
    }
    __syncthreads();

    const int K    = s_K;
    const int init = *d_init;

    // --- phi_0 = e_init ; phi_1 = H' e_init (analytic single column) ---
    float cur[8], prev[8], psr[8], psi[8];
#pragma unroll
    for (int e = 0; e < 4; e++) {
#pragma unroll
        for (int c = 0; c < 2; c++) {
            const int s  = (e << 10) | (tid << 1) | c;
            const int ix = e * 2 + c;
            const float p0 = (s == init) ? 1.f : 0.f;
            float p1 = (s == init) ? diag[ix] : 0.f;
            const int d = s ^ init;
#pragma unroll
            for (int i = 0; i < NQ; i++)
                if (d == (1 << i)) p1 = px[i];
            prev[ix] = p0;
            cur[ix]  = p1;
            psr[ix]  = s_cr[0] * p0;     // k=0 term (real)
            psi[ix]  = s_ci[1] * p1;     // k=1 term (imag)
        }
        buf0[(e << 9) | tid] = make_float2(cur[e * 2], cur[e * 2 + 1]);
    }
    __syncthreads();

    // loop-invariant partner tid for smem-tap bits 1..9
    int pq[9];
#pragma unroll
    for (int b = 1; b <= 9; b++)
        pq[b - 1] = tid ^ (1 << (b - 1));

#define CHEB_STEP(SRC, DST, KK)                                              \
    do {                                                                     \
        float acc[8];                                                        \
        _Pragma("unroll")                                                    \
        for (int e = 0; e < 4; e++) {                                        \
            _Pragma("unroll")                                                \
            for (int c = 0; c < 2; c++) {                                    \
                const int ix = e * 2 + c;                                    \
                float a = diag[ix] * cur[ix];                                \
                a = fmaf(px[0],  cur[e * 2 + (c ^ 1)],       a);             \
                a = fmaf(px[10], cur[(e ^ 1) * 2 + c],       a);             \
                a = fmaf(px[11], cur[(e ^ 2) * 2 + c],       a);             \
                acc[ix] = a;                                                 \
            }                                                                \
        }                                                                    \
        _Pragma("unroll")                                                    \
        for (int bi = 0; bi < 9; bi++) {                                     \
            const float c_ = px[bi + 1];                                     \
            _Pragma("unroll")                                                \
            for (int e = 0; e < 4; e++) {                                    \
                const float2 pv = (SRC)[(e << 9) | pq[bi]];                  \
                acc[e * 2 + 0] = fmaf(c_, pv.x, acc[e * 2 + 0]);             \
                acc[e * 2 + 1] = fmaf(c_, pv.y, acc[e * 2 + 1]);             \
            }                                                                \
        }                                                                    \
        const float cr = s_cr[KK], ci = s_ci[KK];                            \
        _Pragma("unroll")                                                    \
        for (int ix = 0; ix < 8; ix++) {                                     \
            const float nx = fmaf(2.f, acc[ix], -prev[ix]);                  \
            prev[ix] = cur[ix];                                              \
            cur[ix]  = nx;                                                   \
            psr[ix]  = fmaf(cr, nx, psr[ix]);                                \
            psi[ix]  = fmaf(ci, nx, psi[ix]);                                \
        }                                                                    \
        _Pragma("unroll")                                                    \
        for (int e = 0; e < 4; e++)                                          \
            (DST)[(e << 9) | tid] = make_float2(cur[e * 2], cur[e * 2 + 1]); \
        __syncthreads();                                                     \
    } while (0)

    for (int k = 2; k <= K; k += 2) {
        CHEB_STEP(buf0, buf1, k);        // even k: phi in buf0 -> buf1
        if (k + 1 <= K)
            CHEB_STEP(buf1, buf0, k + 1);
    }
#undef CHEB_STEP

#pragma unroll
    for (int e = 0; e < 4; e++) {
#pragma unroll
        for (int c = 0; c < 2; c++) {
            const int s  = (e << 10) | (tid << 1) | c;
            const int ix = e * 2 + c;
            g_states[t][s] = make_float2(psr[ix], psi[ix]);
        }
    }
}

// ---------------------------------------------------------------------------
// Kernel C: per-(t,b) basis rotation, radix-4 fused over non-Z qubits,
// then gather of 256 shot probabilities. 512 threads.
// Pauli position i acts on bit (N-1-i) of the state index.
// ---------------------------------------------------------------------------
__global__ __launch_bounds__(512)
void measure_kernel(const int* __restrict__ d_pauli,
                    const int* __restrict__ d_idx,
                    float* __restrict__ d_out)
{
    __shared__ float re[DIM];
    __shared__ float im[DIM];
    __shared__ int p_raw[NQ];
    __shared__ int nzm[NQ];
    __shared__ int nzp[NQ];
    __shared__ int s_nnz;

    const int tid = threadIdx.x;
    const int b   = blockIdx.x;
    const int t   = blockIdx.y;

    if (tid < NQ) p_raw[tid] = d_pauli[b * NQ + tid];

#pragma unroll
    for (int r = 0; r < DIM / 512; r++) {
        const int s = tid + (r << 9);
        const float2 v = g_states[t][s];
        re[s] = v.x;
        im[s] = v.y;
    }
    __syncthreads();

    if (tid == 0) {
        int c = 0;
        for (int m = NQ - 1; m >= 0; m--) {
            const int p = p_raw[NQ - 1 - m];
            if (p != 2) { nzm[c] = m; nzp[c] = p; c++; }
        }
        s_nnz = c;
    }
    __syncthreads();

    const int nnz = s_nnz;
    int i = 0;
    // radix-4: two non-Z qubits per sweep (mh > ml; list descending)
    for (; i + 1 < nnz; i += 2) {
        const int mh = nzm[i], ml = nzm[i + 1];
        const int ph_ = nzp[i], pl = nzp[i + 1];
        const int lml = (1 << ml) - 1;
        const int lmh = (1 << mh) - 1;
#pragma unroll
        for (int r = 0; r < (DIM / 4) / 512; r++) {
            const int g  = tid + (r << 9);
            const int x  = ((g & ~lml) << 1) | (g & lml);
            const int s00 = ((x & ~lmh) << 1) | (x & lmh);
            const int s01 = s00 | (1 << ml);
            const int s10 = s00 | (1 << mh);
            const int s11 = s10 | (1 << ml);
            const float r00 = re[s00], i00 = im[s00];
            const float r01 = re[s01], i01 = im[s01];
            const float r10 = re[s10], i10 = im[s10];
            const float r11 = re[s11], i11 = im[s11];
            float a0r, a0i, a1r, a1i, b0r, b0i, b1r, b1i;
            if (pl == 0) {
                a0r = r00 + r01; a0i = i00 + i01; a1r = r00 - r01; a1i = i00 - i01;
                b0r = r10 + r11; b0i = i10 + i11; b1r = r10 - r11; b1i = i10 - i11;
            } else {
                a0r = r00 + i01; a0i = i00 - r01; a1r = r00 - i01; a1i = i00 + r01;
                b0r = r10 + i11; b0i = i10 - r11; b1r = r10 - i11; b1i = i10 + r11;
            }
            float o00r, o00i, o01r, o01i, o10r, o10i, o11r, o11i;
            if (ph_ == 0) {
                o00r = a0r + b0r; o00i = a0i + b0i; o10r = a0r - b0r; o10i = a0i - b0i;
                o01r = a1r + b1r; o01i = a1i + b1i; o11r = a1r - b1r; o11i = a1i - b1i;
            } else {
                o00r = a0r + b0i; o00i = a0i - b0r; o10r = a0r - b0i; o10i = a0i + b0r;
                o01r = a1r + b1i; o01i = a1i - b1r; o11r = a1r - b1i; o11i = a1i + b1r;
            }
            re[s00] = o00r * 0.5f; im[s00] = o00i * 0.5f;
            re[s01] = o01r * 0.5f; im[s01] = o01i * 0.5f;
            re[s10] = o10r * 0.5f; im[s10] = o10i * 0.5f;
            re[s11] = o11r * 0.5f; im[s11] = o11i * 0.5f;
        }
        __syncthreads();
    }
    // leftover single non-Z qubit
    if (i < nnz) {
        const int m = nzm[i], p = nzp[i];
        const int lm = (1 << m) - 1;
        const float s2 = 0.70710678118654752f;
#pragma unroll
        for (int r = 0; r < (DIM / 2) / 512; r++) {
            const int q  = tid + (r << 9);
            const int s0 = ((q & ~lm) << 1) | (q & lm);
            const int s1 = s0 | (1 << m);
            const float r0 = re[s0], i0 = im[s0];
            const float r1 = re[s1], i1 = im[s1];
            float nr0, ni0, nr1, ni1;
            if (p == 0) { nr0 = r0 + r1; ni0 = i0 + i1; nr1 = r0 - r1; ni1 = i0 - i1; }
            else        { nr0 = r0 + i1; ni0 = i0 - r1; nr1 = r0 - i1; ni1 = i0 + r1; }
            re[s0] = nr0 * s2; im[s0] = ni0 * s2;
            re[s1] = nr1 * s2; im[s1] = ni1 * s2;
        }
        __syncthreads();
    }

    if (tid < SHOTS) {
        const int base = (t * BB + b) * SHOTS;
        const int idx  = d_idx[base + tid];
        const float pr = re[idx];
        const float pi = im[idx];
        d_out[base + tid] = pr * pr + pi * pi;
    }
}

// ---------------------------------------------------------------------------
extern "C" void kernel_launch(void* const* d_in, const int* in_sizes, int n_in,
                              void* d_out, int out_size)
{
    const int*   d_init  = (const int*)  d_in[0];
    const float* d_ts    = (const float*)d_in[1];
    const int*   d_pauli = (const int*)  d_in[2];
    const int*   d_idx   = (const int*)  d_in[3];
    const float* d_px    = (const float*)d_in[4];
    const float* d_pzz   = (const float*)d_in[5];

    evolve_kernel<<<TT, 512>>>(d_init, d_ts, d_px, d_pzz);
    measure_kernel<<<dim3(BB, TT), 512>>>(d_pauli, d_idx, (float*)d_out);
}

// round 5
// speedup vs baseline: 3.0765x; 1.1275x over previous
#include <cuda_runtime.h>
#include <math.h>
#include <stdint.h>

#define NQ    12
#define DIM   4096
#define TT    8
#define BB    32
#define SHOTS 256
#define KMAX  80

// Evolved states exp(-i t H)|init>, one complex vector per t, plus sync flags.
__device__ float2 g_states[TT][DIM];
__device__ int    g_flag[TT];   // 0 -> not ready, 1 -> ready (self-cleaning)
__device__ int    g_cnt[TT];    // consumer count for self-clean

__device__ __forceinline__ int ld_acquire(const int* p) {
    int v;
    asm volatile("ld.acquire.gpu.s32 %0, [%1];" : "=r"(v) : "l"(p) : "memory");
    return v;
}
__device__ __forceinline__ void st_release(int* p, int v) {
    asm volatile("st.release.gpu.s32 [%0], %1;" :: "l"(p), "r"(v) : "memory");
}

// ---------------------------------------------------------------------------
// Fused persistent kernel. 256 CTAs x 512 threads.
//   bid < 8 : evolve t=bid (Chebyshev, state in smem), publish, then measure (t,0)
//   bid >= 8: wait on flag[t], then measure (t, b) for remaining 248 tasks
// ---------------------------------------------------------------------------
__global__ __launch_bounds__(512, 1)
void fused_kernel(const int* __restrict__ d_init,
                  const float* __restrict__ d_ts,
                  const int* __restrict__ d_pauli,
                  const int* __restrict__ d_idx,
                  const float* __restrict__ d_px,
                  const float* __restrict__ d_pzz,
                  float* __restrict__ d_out)
{
    // shared pool: evolve uses [0, 2*DIM) as two float2 buffers + coeffs after;
    // measure reuses [0, DIM) = re, [DIM, 2*DIM) = im.
    __shared__ __align__(16) float pool[2 * DIM + 2 * (KMAX + 1)];
    __shared__ int s_misc[3 * NQ + 2];   // evolve: [0]=K ; measure: p_raw/nzm/nzp/nnz

    const int tid = threadIdx.x;
    const int bid = blockIdx.x;

    int t, b;
    if (bid < TT) { t = bid; b = 0; }
    else { const int j = bid - TT; t = j / 31; b = 1 + j % 31; }

    if (bid < TT) {
        // ================= EVOLVE (t = bid) =================
        float2* buf0 = reinterpret_cast<float2*>(pool);
        float2* buf1 = buf0 + DIM / 2;
        float*  s_cr = pool + 2 * DIM;
        float*  s_ci = s_cr + (KMAX + 1);

        // parameters + spectral bound
        float px[NQ];
        float lambda = 0.f;
#pragma unroll
        for (int i = 0; i < NQ; i++) { px[i] = d_px[i]; lambda += fabsf(px[i]); }
        float pzz[NQ - 1];
#pragma unroll
        for (int i = 0; i < NQ - 1; i++) { pzz[i] = d_pzz[i]; lambda += fabsf(pzz[i]); }
        if (lambda < 1e-20f) lambda = 1e-20f;
        const float inv_l = 1.0f / lambda;
#pragma unroll
        for (int i = 0; i < NQ; i++) px[i] *= inv_l;

        // scaled diagonal for owned entries: s = (e<<10)|(tid<<1)|c
        float diag[8];
#pragma unroll
        for (int e = 0; e < 4; e++) {
#pragma unroll
            for (int c = 0; c < 2; c++) {
                const int s = (e << 10) | (tid << 1) | c;
                float d = 0.f;
#pragma unroll
                for (int i = 0; i < NQ - 1; i++) {
                    const int bi = (s >> i) & 1;
                    const int bj = (s >> (i + 1)) & 1;
                    d += (bi == bj) ? pzz[i] : -pzz[i];
                }
                diag[e * 2 + c] = d * inv_l;
            }
        }

        // thread 0: Bessel coefficients (Miller downward) + adaptive trim
        if (tid == 0) {
            double x = (double)d_ts[t] * (double)lambda;
            if (x < 1e-5) x = 1e-5;
            int K = (int)ceil(x) + 16;
            if (K > KMAX) K = KMAX;
            if (K < 2)    K = 2;
            const int M = K + 14;
            double v[KMAX + 16];
            v[M] = 1e-30;
            const double inv_x = 1.0 / x;
            double up = 0.0;
            for (int k = M; k >= 1; k--) {
                const double nv = (2.0 * (double)k * inv_x) * v[k] - up;
                up = v[k];
                v[k - 1] = nv;
            }
            double S = v[0];
            for (int m = 2; m <= M; m += 2) S += 2.0 * v[m];
            const double invS = 1.0 / S;
            // adaptive truncation: drop tail terms below 1e-6
            while (K > 2 && fabs(v[K] * invS) < 1e-6) K--;
            for (int k = 0; k <= K; k++) {
                const double Jk = v[k] * invS;
                const double c  = (k == 0) ? Jk : 2.0 * Jk;
                float cr = 0.f, ci = 0.f;
                switch (k & 3) {         // (-i)^k
                    case 0: cr = (float)c;  break;
                    case 1: ci = (float)-c; break;
                    case 2: cr = (float)-c; break;
                    case 3: ci = (float)c;  break;
                }
                s_cr[k] = cr;
                s_ci[k] = ci;
            }
            s_misc[0] = K;
        }
        __syncthreads();

        const int K    = s_misc[0];
        const int init = *d_init;

        // phi_0 = e_init ; phi_1 = H' e_init (analytic single column)
        float cur[8], prev[8], psr[8], psi[8];
#pragma unroll
        for (int e = 0; e < 4; e++) {
#pragma unroll
            for (int c = 0; c < 2; c++) {
                const int s  = (e << 10) | (tid << 1) | c;
                const int ix = e * 2 + c;
                const float p0 = (s == init) ? 1.f : 0.f;
                float p1 = (s == init) ? diag[ix] : 0.f;
                const int d = s ^ init;
#pragma unroll
                for (int i = 0; i < NQ; i++)
                    if (d == (1 << i)) p1 = px[i];
                prev[ix] = p0;
                cur[ix]  = p1;
                psr[ix]  = s_cr[0] * p0;
                psi[ix]  = s_ci[1] * p1;
            }
            buf0[(e << 9) | tid] = make_float2(cur[e * 2], cur[e * 2 + 1]);
        }
        __syncthreads();

        int pq[9];
#pragma unroll
        for (int bb2 = 1; bb2 <= 9; bb2++)
            pq[bb2 - 1] = tid ^ (1 << (bb2 - 1));

#define CHEB_STEP(SRC, DST, KK)                                              \
    do {                                                                     \
        float acc[8];                                                        \
        _Pragma("unroll")                                                    \
        for (int e = 0; e < 4; e++) {                                        \
            _Pragma("unroll")                                                \
            for (int c = 0; c < 2; c++) {                                    \
                const int ix = e * 2 + c;                                    \
                float a = diag[ix] * cur[ix];                                \
                a = fmaf(px[0],  cur[e * 2 + (c ^ 1)], a);                   \
                a = fmaf(px[10], cur[(e ^ 1) * 2 + c], a);                   \
                a = fmaf(px[11], cur[(e ^ 2) * 2 + c], a);                   \
                acc[ix] = a;                                                 \
            }                                                                \
        }                                                                    \
        _Pragma("unroll")                                                    \
        for (int bi = 0; bi < 9; bi++) {                                     \
            const float c_ = px[bi + 1];                                     \
            _Pragma("unroll")                                                \
            for (int e = 0; e < 4; e++) {                                    \
                const float2 pv = (SRC)[(e << 9) | pq[bi]];                  \
                acc[e * 2 + 0] = fmaf(c_, pv.x, acc[e * 2 + 0]);             \
                acc[e * 2 + 1] = fmaf(c_, pv.y, acc[e * 2 + 1]);             \
            }                                                                \
        }                                                                    \
        const float cr = s_cr[KK], ci = s_ci[KK];                            \
        _Pragma("unroll")                                                    \
        for (int ix = 0; ix < 8; ix++) {                                     \
            const float nx = fmaf(2.f, acc[ix], -prev[ix]);                  \
            prev[ix] = cur[ix];                                              \
            cur[ix]  = nx;                                                   \
            psr[ix]  = fmaf(cr, nx, psr[ix]);                                \
            psi[ix]  = fmaf(ci, nx, psi[ix]);                                \
        }                                                                    \
        _Pragma("unroll")                                                    \
        for (int e = 0; e < 4; e++)                                          \
            (DST)[(e << 9) | tid] = make_float2(cur[e * 2], cur[e * 2 + 1]); \
        __syncthreads();                                                     \
    } while (0)

        for (int k = 2; k <= K; k += 2) {
            CHEB_STEP(buf0, buf1, k);
            if (k + 1 <= K)
                CHEB_STEP(buf1, buf0, k + 1);
        }
#undef CHEB_STEP

        // publish state + release flag
#pragma unroll
        for (int e = 0; e < 4; e++) {
#pragma unroll
            for (int c = 0; c < 2; c++) {
                const int s  = (e << 10) | (tid << 1) | c;
                const int ix = e * 2 + c;
                g_states[t][s] = make_float2(psr[ix], psi[ix]);
            }
        }
        __syncthreads();
        if (tid == 0) {
            __threadfence();
            st_release(&g_flag[t], 1);
        }
        __syncthreads();   // pool reuse guard before measure phase
    } else {
        // ================= WAIT on evolve(t) =================
        if (tid == 0) {
            while (ld_acquire(&g_flag[t]) == 0) __nanosleep(128);
            const int n = atomicAdd(&g_cnt[t], 1);
            if (n == 30) {               // last of 31 waiters: self-clean
                g_cnt[t]  = 0;
                g_flag[t] = 0;
            }
        }
        __syncthreads();
    }

    // ================= MEASURE (t, b) =================
    {
        float* re = pool;
        float* im = pool + DIM;
        int* p_raw = s_misc;
        int* nzm   = s_misc + NQ;
        int* nzp   = s_misc + 2 * NQ;
        int* s_nnz = s_misc + 3 * NQ;

        if (tid < NQ) p_raw[tid] = d_pauli[b * NQ + tid];

#pragma unroll
        for (int r = 0; r < DIM / 512; r++) {
            const int s = tid + (r << 9);
            const float2 v = __ldcg(&g_states[t][s]);
            re[s] = v.x;
            im[s] = v.y;
        }
        __syncthreads();

        if (tid == 0) {
            int c = 0;
            for (int m = NQ - 1; m >= 0; m--) {
                const int p = p_raw[NQ - 1 - m];
                if (p != 2) { nzm[c] = m; nzp[c] = p; c++; }
            }
            *s_nnz = c;
        }
        __syncthreads();

        const int nnz = *s_nnz;
        int i = 0;
        // radix-4: two non-Z qubits per sweep (mh > ml; list descending)
        for (; i + 1 < nnz; i += 2) {
            const int mh = nzm[i], ml = nzm[i + 1];
            const int ph_ = nzp[i], pl = nzp[i + 1];
            const int lml = (1 << ml) - 1;
            const int lmh = (1 << mh) - 1;
#pragma unroll
            for (int r = 0; r < (DIM / 4) / 512; r++) {
                const int g  = tid + (r << 9);
                const int x  = ((g & ~lml) << 1) | (g & lml);
                const int s00 = ((x & ~lmh) << 1) | (x & lmh);
                const int s01 = s00 | (1 << ml);
                const int s10 = s00 | (1 << mh);
                const int s11 = s10 | (1 << ml);
                const float r00 = re[s00], i00 = im[s00];
                const float r01 = re[s01], i01 = im[s01];
                const float r10 = re[s10], i10 = im[s10];
                const float r11 = re[s11], i11 = im[s11];
                float a0r, a0i, a1r, a1i, b0r, b0i, b1r, b1i;
                if (pl == 0) {
                    a0r = r00 + r01; a0i = i00 + i01; a1r = r00 - r01; a1i = i00 - i01;
                    b0r = r10 + r11; b0i = i10 + i11; b1r = r10 - r11; b1i = i10 - i11;
                } else {
                    a0r = r00 + i01; a0i = i00 - r01; a1r = r00 - i01; a1i = i00 + r01;
                    b0r = r10 + i11; b0i = i10 - r11; b1r = r10 - i11; b1i = i10 + r11;
                }
                float o00r, o00i, o01r, o01i, o10r, o10i, o11r, o11i;
                if (ph_ == 0) {
                    o00r = a0r + b0r; o00i = a0i + b0i; o10r = a0r - b0r; o10i = a0i - b0i;
                    o01r = a1r + b1r; o01i = a1i + b1i; o11r = a1r - b1r; o11i = a1i - b1i;
                } else {
                    o00r = a0r + b0i; o00i = a0i - b0r; o10r = a0r - b0i; o10i = a0i + b0r;
                    o01r = a1r + b1i; o01i = a1i - b1r; o11r = a1r - b1i; o11i = a1i + b1r;
                }
                re[s00] = o00r * 0.5f; im[s00] = o00i * 0.5f;
                re[s01] = o01r * 0.5f; im[s01] = o01i * 0.5f;
                re[s10] = o10r * 0.5f; im[s10] = o10i * 0.5f;
                re[s11] = o11r * 0.5f; im[s11] = o11i * 0.5f;
            }
            __syncthreads();
        }
        // leftover single non-Z qubit
        if (i < nnz) {
            const int m = nzm[i], p = nzp[i];
            const int lm = (1 << m) - 1;
            const float s2 = 0.70710678118654752f;
#pragma unroll
            for (int r = 0; r < (DIM / 2) / 512; r++) {
                const int q  = tid + (r << 9);
                const int s0 = ((q & ~lm) << 1) | (q & lm);
                const int s1 = s0 | (1 << m);
                const float r0 = re[s0], i0 = im[s0];
                const float r1 = re[s1], i1 = im[s1];
                float nr0, ni0, nr1, ni1;
                if (p == 0) { nr0 = r0 + r1; ni0 = i0 + i1; nr1 = r0 - r1; ni1 = i0 - i1; }
                else        { nr0 = r0 + i1; ni0 = i0 - r1; nr1 = r0 - i1; ni1 = i0 + r1; }
                re[s0] = nr0 * s2; im[s0] = ni0 * s2;
                re[s1] = nr1 * s2; im[s1] = ni1 * s2;
            }
            __syncthreads();
        }

        if (tid < SHOTS) {
            const int base = (t * BB + b) * SHOTS;
            const int idx  = d_idx[base + tid];
            const float pr = re[idx];
            const float pi = im[idx];
            d_out[base + tid] = pr * pr + pi * pi;
        }
    }
}

// ---------------------------------------------------------------------------
extern "C" void kernel_launch(void* const* d_in, const int* in_sizes, int n_in,
                              void* d_out, int out_size)
{
    const int*   d_init  = (const int*)  d_in[0];
    const float* d_ts    = (const float*)d_in[1];
    const int*   d_pauli = (const int*)  d_in[2];
    const int*   d_idx   = (const int*)  d_in[3];
    const float* d_px    = (const float*)d_in[4];
    const float* d_pzz   = (const float*)d_in[5];

    fused_kernel<<<TT * BB, 512>>>(d_init, d_ts, d_pauli, d_idx,
                                   d_px, d_pzz, (float*)d_out);
}